// round 5
// baseline (speedup 1.0000x reference)
#include <cuda_runtime.h>
#include <cstdint>

// Problem constants
#define D1_  270
#define K_   32
#define C_   60
#define B_   64
#define T_   4096
#define P_   (K_*K_)          // 1024

// gemm tiling
#define JT   96               // j per block (3 blocks cover 270 with padding)
#define JR   6                // j per thread
#define TPRS 4                // t-pairs per thread (8 t)
#define CCH  30               // c chunk staged in smem (2 chunks of 30)

// ---------------- device scratch (no allocation allowed) ----------------
__device__ float g_ct[P_ * C_];     // cos(phase)[p][c]
__device__ float g_st[P_ * C_];     // sin(phase)[p][c]
__device__ float g_w [D1_ * C_];    // softmax weights [j][c]

// ---------------- packed f32x2 helpers (Blackwell) ----------------
__device__ __forceinline__ unsigned long long fma2(unsigned long long a,
                                                   unsigned long long b,
                                                   unsigned long long c) {
    unsigned long long d;
    asm("fma.rn.f32x2 %0, %1, %2, %3;" : "=l"(d) : "l"(a), "l"(b), "l"(c));
    return d;
}
__device__ __forceinline__ unsigned long long pack2(float v) {
    unsigned long long d;
    asm("mov.b64 %0, {%1, %1};" : "=l"(d) : "f"(v));
    return d;
}

// ---------------- kernel 1: trig tables (double-precision phase) --------
__global__ void trig_kernel(const float* __restrict__ loc) {
    int i = blockIdx.x * 256 + threadIdx.x;
    if (i >= P_ * C_) return;
    int p = i / C_, c = i - p * C_;
    int k = p >> 5, l = p & 31;
    double x = (double)loc[2 * c];
    double y = (double)loc[2 * c + 1];
    double ph = 6.283185307179586476925286766559 * ((double)k * x + (double)l * y);
    double s, co;
    sincos(ph, &s, &co);
    g_ct[i] = (float)co;
    g_st[i] = (float)s;
}

// ---------------- kernel 2: a = z . trig, softmax over c ---------------
__global__ void weights_kernel(const float* __restrict__ zre,
                               const float* __restrict__ zim) {
    int j   = blockIdx.x;          // 0..269
    int tid = threadIdx.x;         // 256
    int s = tid >> 6, c = tid & 63;
    __shared__ float partial[256];
    __shared__ float ex[64];
    __shared__ float tot;

    float acc = 0.f;
    if (c < C_) {
        const float* zr = zre + j * P_;
        const float* zi = zim + j * P_;
        int p0 = s * 256;
        #pragma unroll 4
        for (int p = p0; p < p0 + 256; p++) {
            acc += zr[p] * g_ct[p * C_ + c] + zi[p] * g_st[p * C_ + c];
        }
    }
    partial[tid] = acc;
    __syncthreads();
    if (s == 0 && c < C_) {
        float a = partial[c] + partial[64 + c] + partial[128 + c] + partial[192 + c];
        ex[c] = expf(a);
    }
    __syncthreads();
    if (tid == 0) {
        float t = 0.f;
        #pragma unroll
        for (int i = 0; i < C_; i++) t += ex[i];
        tot = t;
    }
    __syncthreads();
    if (s == 0 && c < C_) g_w[j * C_ + c] = ex[c] / tot;
}

// ---------------- kernel 3: out[b,j,t] = sum_c w[j,c] X[b,c,t] ----------
// grid (32 t-tiles, 3 j-blocks, 64 batches), 256 threads.
// thread = (tt in 0..15, tj in 0..15); computes JR=6 j x 4 t-pairs.
__global__ void __launch_bounds__(256, 2)
gemm_kernel(const float* __restrict__ X, float* __restrict__ out) {
    __shared__ unsigned long long Xs[CCH * 64];   // 30 c-rows x 64 t-pairs (15.4 KB)
    __shared__ float Ws[JT * C_];                 // 96 x 60 (23 KB)

    int tid = threadIdx.x;
    int tt = tid & 15;
    int tj = tid >> 4;
    int t0 = blockIdx.x * 128;
    int j0 = blockIdx.y * JT;
    int b  = blockIdx.z;

    // stage weights (zero-pad j >= 270)
    for (int idx = tid; idx < JT * C_; idx += 256) {
        int jj = idx / C_, c = idx - jj * C_;
        int j = j0 + jj;
        Ws[idx] = (j < D1_) ? g_w[j * C_ + c] : 0.f;
    }

    unsigned long long acc[JR][TPRS];
    #pragma unroll
    for (int u = 0; u < JR; u++)
        #pragma unroll
        for (int p = 0; p < TPRS; p++) acc[u][p] = 0ull;

    const float* Xb = X + (size_t)b * C_ * T_ + t0;

    for (int ch = 0; ch < 2; ch++) {
        __syncthreads();   // also makes Ws visible before first compute pass
        for (int idx = tid; idx < CCH * 64; idx += 256) {
            int cc = idx >> 6, q = idx & 63;
            int c = ch * CCH + cc;
            Xs[idx] = *(const unsigned long long*)(Xb + (size_t)c * T_ + q * 2);
        }
        __syncthreads();

        #pragma unroll 6
        for (int cc = 0; cc < CCH; cc++) {
            int c = ch * CCH + cc;
            unsigned long long xp[TPRS];
            #pragma unroll
            for (int p = 0; p < TPRS; p++) xp[p] = Xs[cc * 64 + tt + 16 * p];
            #pragma unroll
            for (int u = 0; u < JR; u++) {
                unsigned long long wp = pack2(Ws[(tj * JR + u) * C_ + c]);
                #pragma unroll
                for (int p = 0; p < TPRS; p++) acc[u][p] = fma2(wp, xp[p], acc[u][p]);
            }
        }
    }

    // store (vectorized float2)
    #pragma unroll
    for (int u = 0; u < JR; u++) {
        int j = j0 + tj * JR + u;
        if (j < D1_) {
            float2* orow = (float2*)(out + ((size_t)b * D1_ + j) * T_ + t0);
            #pragma unroll
            for (int p = 0; p < TPRS; p++) {
                orow[tt + 16 * p] = *(float2*)&acc[u][p];
            }
        }
    }
}

// ---------------- launch ----------------
extern "C" void kernel_launch(void* const* d_in, const int* in_sizes, int n_in,
                              void* d_out, int out_size) {
    const float* X   = (const float*)d_in[0];   // [64, 60, 4096]
    const float* zre = (const float*)d_in[1];   // [270, 32, 32]
    const float* zim = (const float*)d_in[2];   // [270, 32, 32]
    const float* loc = (const float*)d_in[3];   // [60, 2]
    float* out = (float*)d_out;                 // [64, 270, 4096]

    trig_kernel<<<(P_ * C_ + 255) / 256, 256>>>(loc);
    weights_kernel<<<D1_, 256>>>(zre, zim);
    dim3 grid(T_ / 128, (D1_ + JT - 1) / JT, B_);
    gemm_kernel<<<grid, 256>>>(X, out);
}